// round 5
// baseline (speedup 1.0000x reference)
#include <cuda_runtime.h>
#include <cuda_bf16.h>
#include <cstdint>

// CumulativeNormalizer: x [32, 512, 4000] fp32.
// out[b, f, t] = (x[t] - mean(x[0..t])) / sqrt(var(x[0..t]) + 1e-4)
// One warp per row; 128 frames per warp-iteration (float4 per lane + warp scan).

#define FRAMES 4000
#define ROWS   (32 * 512)
#define EPS    1e-4f
#define WARPS_PER_BLOCK 8
#define BLOCK_THREADS   (WARPS_PER_BLOCK * 32)

__global__ __launch_bounds__(BLOCK_THREADS)
void cumnorm_kernel(const float* __restrict__ x, float* __restrict__ out) {
    // Shared table of 1/count so the hot loop needs no per-element RCP.
    __shared__ float s_inv[FRAMES];
    for (int i = threadIdx.x; i < FRAMES; i += BLOCK_THREADS)
        s_inv[i] = 1.0f / (float)(i + 1);
    __syncthreads();

    const int warp_id = threadIdx.x >> 5;
    const int lane    = threadIdx.x & 31;
    const int row     = blockIdx.x * WARPS_PER_BLOCK + warp_id;
    if (row >= ROWS) return;

    const float* __restrict__ xr = x   + (size_t)row * FRAMES;
    float*       __restrict__ yr = out + (size_t)row * FRAMES;

    float carry_s = 0.0f;   // running sum of x over frames already done
    float carry_q = 0.0f;   // running sum of x*x

    const unsigned FULL = 0xFFFFFFFFu;

    for (int base = 0; base < FRAMES; base += 128) {
        const int idx = base + lane * 4;
        float4 v = make_float4(0.f, 0.f, 0.f, 0.f);
        const bool active = (idx < FRAMES);   // FRAMES % 4 == 0 -> whole float4 valid
        if (active) v = *reinterpret_cast<const float4*>(xr + idx);

        // Local inclusive prefix over this lane's 4 elements.
        const float l1 = v.x;
        const float l2 = l1 + v.y;
        const float l3 = l2 + v.z;
        const float l4 = l3 + v.w;
        const float m1 = v.x * v.x;
        const float m2 = fmaf(v.y, v.y, m1);
        const float m3 = fmaf(v.z, v.z, m2);
        const float m4 = fmaf(v.w, v.w, m3);

        // Warp inclusive scan over per-lane totals (l4, m4).
        float s = l4, q = m4;
        #pragma unroll
        for (int off = 1; off < 32; off <<= 1) {
            float ts = __shfl_up_sync(FULL, s, off);
            float tq = __shfl_up_sync(FULL, q, off);
            if (lane >= off) { s += ts; q += tq; }
        }
        // Exclusive prefix for this lane + row carry.
        const float base_s = carry_s + (s - l4);
        const float base_q = carry_q + (q - m4);
        // Advance the row carry by this chunk's warp total.
        carry_s += __shfl_sync(FULL, s, 31);
        carry_q += __shfl_sync(FULL, q, 31);

        if (active) {
            const float4 inv = *reinterpret_cast<const float4*>(&s_inv[idx]);
            float4 o;

            {
                const float S = base_s + l1, Q = base_q + m1;
                const float mean = S * inv.x;
                const float var  = fmaf(Q, inv.x, -mean * mean);
                o.x = (v.x - mean) * rsqrtf(var + EPS);
            }
            {
                const float S = base_s + l2, Q = base_q + m2;
                const float mean = S * inv.y;
                const float var  = fmaf(Q, inv.y, -mean * mean);
                o.y = (v.y - mean) * rsqrtf(var + EPS);
            }
            {
                const float S = base_s + l3, Q = base_q + m3;
                const float mean = S * inv.z;
                const float var  = fmaf(Q, inv.z, -mean * mean);
                o.z = (v.z - mean) * rsqrtf(var + EPS);
            }
            {
                const float S = base_s + l4, Q = base_q + m4;
                const float mean = S * inv.w;
                const float var  = fmaf(Q, inv.w, -mean * mean);
                o.w = (v.w - mean) * rsqrtf(var + EPS);
            }

            *reinterpret_cast<float4*>(yr + idx) = o;
        }
    }
}

extern "C" void kernel_launch(void* const* d_in, const int* in_sizes, int n_in,
                              void* d_out, int out_size) {
    const float* x = (const float*)d_in[0];
    float* out = (float*)d_out;
    (void)in_sizes; (void)n_in; (void)out_size;

    const int grid = ROWS / WARPS_PER_BLOCK;   // 16384 / 8 = 2048 blocks
    cumnorm_kernel<<<grid, BLOCK_THREADS>>>(x, out);
}

// round 6
// speedup vs baseline: 1.0159x; 1.0159x over previous
#include <cuda_runtime.h>
#include <cuda_bf16.h>
#include <cstdint>

// CumulativeNormalizer: x [32, 512, 4000] fp32.
// out[b, f, t] = (x[t] - mean(x[0..t])) / sqrt(var(x[0..t]) + 1e-4)
// One warp per row; 256 frames per warp-iteration (2x float4 per lane,
// 8-element local prefix + one warp scan), software-pipelined loads.

#define FRAMES 4000
#define ROWS   (32 * 512)
#define EPS    1e-4f
#define WARPS_PER_BLOCK 8
#define BLOCK_THREADS   (WARPS_PER_BLOCK * 32)
#define CHUNK   256
#define NITERS  ((FRAMES + CHUNK - 1) / CHUNK)   // 16

__global__ __launch_bounds__(BLOCK_THREADS)
void cumnorm_kernel(const float* __restrict__ x, float* __restrict__ out) {
    // Shared table of 1/count so the hot loop needs no per-element RCP.
    __shared__ float s_inv[FRAMES];
    for (int i = threadIdx.x; i < FRAMES; i += BLOCK_THREADS)
        s_inv[i] = 1.0f / (float)(i + 1);
    __syncthreads();

    const int warp_id = threadIdx.x >> 5;
    const int lane    = threadIdx.x & 31;
    const int row     = blockIdx.x * WARPS_PER_BLOCK + warp_id;

    const float* __restrict__ xr = x   + (size_t)row * FRAMES;
    float*       __restrict__ yr = out + (size_t)row * FRAMES;

    float carry_s = 0.0f;   // running sum of x
    float carry_q = 0.0f;   // running sum of x*x

    const unsigned FULL = 0xFFFFFFFFu;
    const int lo = lane * 8;          // lane's offset within a 256-frame chunk

    // Prologue: load chunk 0 (always fully in-bounds: 248+7 < 4000).
    float4 va = __ldcs(reinterpret_cast<const float4*>(xr + lo));
    float4 vb = __ldcs(reinterpret_cast<const float4*>(xr + lo + 4));

    #pragma unroll 1
    for (int it = 0; it < NITERS; ++it) {
        const int idx  = it * CHUNK + lo;
        const int nidx = idx + CHUNK;

        // Prefetch next chunk (independent of the carry chain).
        float4 na = make_float4(0.f, 0.f, 0.f, 0.f);
        float4 nb = make_float4(0.f, 0.f, 0.f, 0.f);
        if (nidx < FRAMES) {          // FRAMES % 8 == 0 -> all-or-nothing per lane
            na = __ldcs(reinterpret_cast<const float4*>(xr + nidx));
            nb = __ldcs(reinterpret_cast<const float4*>(xr + nidx + 4));
        }

        const bool act = (idx < FRAMES);   // inactive lanes hold zeros (from guard above)

        // Local inclusive prefix over this lane's 8 elements.
        const float l1 = va.x;
        const float l2 = l1 + va.y;
        const float l3 = l2 + va.z;
        const float l4 = l3 + va.w;
        const float l5 = l4 + vb.x;
        const float l6 = l5 + vb.y;
        const float l7 = l6 + vb.z;
        const float l8 = l7 + vb.w;
        const float m1 = va.x * va.x;
        const float m2 = fmaf(va.y, va.y, m1);
        const float m3 = fmaf(va.z, va.z, m2);
        const float m4 = fmaf(va.w, va.w, m3);
        const float m5 = fmaf(vb.x, vb.x, m4);
        const float m6 = fmaf(vb.y, vb.y, m5);
        const float m7 = fmaf(vb.z, vb.z, m6);
        const float m8 = fmaf(vb.w, vb.w, m7);

        // Warp inclusive scan over per-lane totals.
        float s = l8, q = m8;
        #pragma unroll
        for (int off = 1; off < 32; off <<= 1) {
            float ts = __shfl_up_sync(FULL, s, off);
            float tq = __shfl_up_sync(FULL, q, off);
            if (lane >= off) { s += ts; q += tq; }
        }
        const float base_s = carry_s + (s - l8);
        const float base_q = carry_q + (q - m8);
        carry_s += __shfl_sync(FULL, s, 31);
        carry_q += __shfl_sync(FULL, q, 31);

        if (act) {
            const float4 i0 = *reinterpret_cast<const float4*>(&s_inv[idx]);
            const float4 i1 = *reinterpret_cast<const float4*>(&s_inv[idx + 4]);
            float4 oa, ob;

            {   const float S = base_s + l1, Q = base_q + m1;
                const float mean = S * i0.x;
                const float var  = fmaf(Q, i0.x, -mean * mean);
                oa.x = (va.x - mean) * rsqrtf(var + EPS); }
            {   const float S = base_s + l2, Q = base_q + m2;
                const float mean = S * i0.y;
                const float var  = fmaf(Q, i0.y, -mean * mean);
                oa.y = (va.y - mean) * rsqrtf(var + EPS); }
            {   const float S = base_s + l3, Q = base_q + m3;
                const float mean = S * i0.z;
                const float var  = fmaf(Q, i0.z, -mean * mean);
                oa.z = (va.z - mean) * rsqrtf(var + EPS); }
            {   const float S = base_s + l4, Q = base_q + m4;
                const float mean = S * i0.w;
                const float var  = fmaf(Q, i0.w, -mean * mean);
                oa.w = (va.w - mean) * rsqrtf(var + EPS); }
            {   const float S = base_s + l5, Q = base_q + m5;
                const float mean = S * i1.x;
                const float var  = fmaf(Q, i1.x, -mean * mean);
                ob.x = (vb.x - mean) * rsqrtf(var + EPS); }
            {   const float S = base_s + l6, Q = base_q + m6;
                const float mean = S * i1.y;
                const float var  = fmaf(Q, i1.y, -mean * mean);
                ob.y = (vb.y - mean) * rsqrtf(var + EPS); }
            {   const float S = base_s + l7, Q = base_q + m7;
                const float mean = S * i1.z;
                const float var  = fmaf(Q, i1.z, -mean * mean);
                ob.z = (vb.z - mean) * rsqrtf(var + EPS); }
            {   const float S = base_s + l8, Q = base_q + m8;
                const float mean = S * i1.w;
                const float var  = fmaf(Q, i1.w, -mean * mean);
                ob.w = (vb.w - mean) * rsqrtf(var + EPS); }

            __stcs(reinterpret_cast<float4*>(yr + idx),     oa);
            __stcs(reinterpret_cast<float4*>(yr + idx + 4), ob);
        }

        va = na; vb = nb;
    }
}

extern "C" void kernel_launch(void* const* d_in, const int* in_sizes, int n_in,
                              void* d_out, int out_size) {
    const float* x = (const float*)d_in[0];
    float* out = (float*)d_out;
    (void)in_sizes; (void)n_in; (void)out_size;

    const int grid = ROWS / WARPS_PER_BLOCK;   // 2048 blocks
    cumnorm_kernel<<<grid, BLOCK_THREADS>>>(x, out);
}

// round 7
// speedup vs baseline: 1.2174x; 1.1982x over previous
#include <cuda_runtime.h>
#include <cuda_bf16.h>
#include <cstdint>

// CumulativeNormalizer: x [32, 512, 4000] fp32.
// out[b,f,t] = (x[t] - mean(x[0..t])) / sqrt(var(x[0..t]) + 1e-4)
//
// One 256-thread block per row. Row staged to shared via cp.async (padded,
// bank-conflict-free), thread-local 16-elem prefix + warp scan + cross-warp
// combine, epilogue in place, coalesced streaming store.
// Identity used: (x - S/c)/sqrt(Q/c - (S/c)^2 + eps)
//              = (x*c - S) * rsqrt(c*Q - S*S + eps*c*c)   -> 1 MUFU/elem.

#define FRAMES  4000
#define ROWS    (32 * 512)
#define EPS     1e-4f
#define THREADS 256
#define SEG     16
#define ACTIVE  250                      // 250 * 16 = 4000
#define VEC4    (FRAMES / 4)             // 1000 float4 per row
#define PADDED  (FRAMES + 4 * (FRAMES / 32))   // 4500 floats

__device__ __forceinline__ int padi(int i) { return i + ((i >> 5) << 2); }

__global__ __launch_bounds__(THREADS)
void cumnorm_kernel(const float* __restrict__ x, float* __restrict__ out) {
    __shared__ float sd[PADDED];
    __shared__ float swS[8];
    __shared__ float swQ[8];

    const int tid  = threadIdx.x;
    const int lane = tid & 31;
    const int w    = tid >> 5;
    const int row  = blockIdx.x;

    const float* __restrict__ xr = x   + (size_t)row * FRAMES;
    float*       __restrict__ yr = out + (size_t)row * FRAMES;

    // ---- Stage row -> shared (cp.async.cg, coalesced, padded dst) ----
    const unsigned sbase = (unsigned)__cvta_generic_to_shared(sd);
    #pragma unroll
    for (int k = 0; k < 4; k++) {
        const int i4 = tid + THREADS * k;
        if (i4 < VEC4) {
            const int g = i4 * 4;
            const unsigned dst = sbase + (unsigned)(padi(g) * 4);
            asm volatile("cp.async.cg.shared.global [%0], [%1], 16;\n"
                         :: "r"(dst), "l"(xr + g));
        }
    }
    asm volatile("cp.async.commit_group;\n");
    asm volatile("cp.async.wait_group 0;\n");
    __syncthreads();

    // ---- Per-thread segment totals (S, Q) over 16 contiguous frames ----
    float S = 0.f, Q = 0.f;
    if (tid < ACTIVE) {
        const int p0 = padi(tid * SEG);   // segment is contiguous in padded space
        #pragma unroll
        for (int j = 0; j < 4; j++) {
            const float4 v = *reinterpret_cast<const float4*>(&sd[p0 + 4 * j]);
            S += v.x + v.y + v.z + v.w;
            Q = fmaf(v.x, v.x, Q);
            Q = fmaf(v.y, v.y, Q);
            Q = fmaf(v.z, v.z, Q);
            Q = fmaf(v.w, v.w, Q);
        }
    }

    // ---- Warp inclusive scan over segment totals ----
    const unsigned FULL = 0xFFFFFFFFu;
    float is = S, iq = Q;
    #pragma unroll
    for (int off = 1; off < 32; off <<= 1) {
        const float ts = __shfl_up_sync(FULL, is, off);
        const float tq = __shfl_up_sync(FULL, iq, off);
        if (lane >= off) { is += ts; iq += tq; }
    }
    if (lane == 31) { swS[w] = is; swQ[w] = iq; }
    __syncthreads();

    // ---- Cross-warp exclusive offset (8 warps, broadcast reads) ----
    float offS = 0.f, offQ = 0.f;
    #pragma unroll
    for (int ww = 0; ww < 7; ww++) {
        if (ww < w) { offS += swS[ww]; offQ += swQ[ww]; }
    }
    const float baseS = offS + (is - S);   // exclusive prefix before this segment
    const float baseQ = offQ + (iq - Q);

    // ---- Epilogue: running accumulate inside segment, normalize in place ----
    if (tid < ACTIVE) {
        const int p0 = padi(tid * SEG);
        float s = baseS, q = baseQ;
        float c = (float)(tid * SEG + 1);   // count of first element in segment
        #pragma unroll
        for (int j = 0; j < 4; j++) {
            const float4 v = *reinterpret_cast<const float4*>(&sd[p0 + 4 * j]);
            float4 o;
            {
                s += v.x; q = fmaf(v.x, v.x, q);
                float t = fmaf(c, q, -s * s);
                t = fmaf(EPS * c, c, t);
                o.x = fmaf(v.x, c, -s) * rsqrtf(t);
                c += 1.0f;
            }
            {
                s += v.y; q = fmaf(v.y, v.y, q);
                float t = fmaf(c, q, -s * s);
                t = fmaf(EPS * c, c, t);
                o.y = fmaf(v.y, c, -s) * rsqrtf(t);
                c += 1.0f;
            }
            {
                s += v.z; q = fmaf(v.z, v.z, q);
                float t = fmaf(c, q, -s * s);
                t = fmaf(EPS * c, c, t);
                o.z = fmaf(v.z, c, -s) * rsqrtf(t);
                c += 1.0f;
            }
            {
                s += v.w; q = fmaf(v.w, v.w, q);
                float t = fmaf(c, q, -s * s);
                t = fmaf(EPS * c, c, t);
                o.w = fmaf(v.w, c, -s) * rsqrtf(t);
                c += 1.0f;
            }
            *reinterpret_cast<float4*>(&sd[p0 + 4 * j]) = o;   // own slots only
        }
    }
    __syncthreads();

    // ---- Unstage: shared -> global, coalesced streaming stores ----
    #pragma unroll
    for (int k = 0; k < 4; k++) {
        const int i4 = tid + THREADS * k;
        if (i4 < VEC4) {
            const int g = i4 * 4;
            const float4 v = *reinterpret_cast<const float4*>(&sd[padi(g)]);
            __stcs(reinterpret_cast<float4*>(yr + g), v);
        }
    }
}

extern "C" void kernel_launch(void* const* d_in, const int* in_sizes, int n_in,
                              void* d_out, int out_size) {
    const float* x = (const float*)d_in[0];
    float* out = (float*)d_out;
    (void)in_sizes; (void)n_in; (void)out_size;

    cumnorm_kernel<<<ROWS, THREADS>>>(x, out);   // one block per row
}